// round 17
// baseline (speedup 1.0000x reference)
#include <cuda_runtime.h>
#include <cstdint>

#define BATCH 8
#define NVAL  261888
#define PRE   6000
#define CAP   8192
#define CAPW  3072
#define PROP  1000
#define W     2048         // NMS window (exact top-W sorted)
#define MWORDS 64          // matrix row words (W/32)
#define FULLM 0xFFFFFFFFu
#define HBLK  64           // blocks for hist/compact stages (per batch)

// ---------------- scratch (static device globals; no allocation) ----------------
__device__ unsigned           g_u[BATCH * NVAL];
__device__ unsigned           g_hist1[BATCH * 65536];
__device__ unsigned           g_b1p[BATCH];
__device__ unsigned           g_b1w[BATCH];
__device__ unsigned           g_abovew[BATCH];
__device__ int                g_candcnt[BATCH];
__device__ int                g_topcnt[BATCH];
__device__ int                g_wvalid[BATCH];
__device__ unsigned           g_done1[BATCH];   // zero-init; reset by last block
__device__ unsigned           g_done2[BATCH];
__device__ unsigned long long g_cand[BATCH * CAP];
__device__ unsigned long long g_top[BATCH * CAPW];
__device__ float              g_winbox[BATCH * W * 4];
__device__ unsigned           g_walive[BATCH * 64];
__device__ unsigned           g_mat[(size_t)BATCH * W * MWORDS];    // row-major, 4 MB
__device__ float              g_fbb[BATCH * CAP * 4];
__device__ int                g_picks[BATCH * PROP];
__device__ int                g_fbcount[BATCH];
__device__ int                g_fbneed[BATCH];

// ---------------- streams/events created at program load ----------------------
struct StreamSet {
    cudaStream_t s[BATCH];
    cudaEvent_t  root;
    cudaEvent_t  done[BATCH];
    StreamSet() {
        for (int i = 0; i < BATCH; ++i)
            cudaStreamCreateWithFlags(&s[i], cudaStreamNonBlocking);
        cudaEventCreateWithFlags(&root, cudaEventDisableTiming);
        for (int i = 0; i < BATCH; ++i)
            cudaEventCreateWithFlags(&done[i], cudaEventDisableTiming);
    }
};
static StreamSet g_ss;

__device__ __forceinline__ unsigned flip_f(float f) {
    unsigned b = __float_as_uint(f);
    unsigned mask = (unsigned)((int)b >> 31) | 0x80000000u;
    return b ^ mask;
}
__device__ __forceinline__ float unflip_f(unsigned u) {
    unsigned mask = (u >> 31) ? 0x80000000u : 0xFFFFFFFFu;
    return __uint_as_float(u ^ mask);
}

__device__ __forceinline__ float4 compute_box(const float* __restrict__ bbox,
                                              const float* __restrict__ anchors,
                                              int b, int idx) {
    int base = (b * NVAL + idx) * 4;
    float ay1 = anchors[base + 0];
    float ax1 = anchors[base + 1];
    float ay2 = anchors[base + 2];
    float ax2 = anchors[base + 3];
    float d0 = bbox[base + 0] * 0.1f;
    float d1 = bbox[base + 1] * 0.1f;
    float d2 = bbox[base + 2] * 0.2f;
    float d3 = bbox[base + 3] * 0.2f;
    float h = ay2 - ay1;
    float w = ax2 - ax1;
    float cy = ay1 + 0.5f * h;
    float cx = ax1 + 0.5f * w;
    cy = cy + d0 * h;
    cx = cx + d1 * w;
    h = h * expf(d2);
    w = w * expf(d3);
    float y1 = cy - 0.5f * h;
    float x1 = cx - 0.5f * w;
    float y2 = y1 + h;
    float x2 = x1 + w;
    return make_float4(fminf(fmaxf(y1, 0.f), 1.f),
                       fminf(fmaxf(x1, 0.f), 1.f),
                       fminf(fmaxf(y2, 0.f), 1.f),
                       fminf(fmaxf(x2, 0.f), 1.f));
}

__device__ __forceinline__ bool iou_ge07(float4 a, float fa, float4 c) {
    float yy1 = fmaxf(a.x, c.x);
    float xx1 = fmaxf(a.y, c.y);
    float yy2 = fminf(a.z, c.z);
    float xx2 = fminf(a.w, c.w);
    float inter = fmaxf(yy2 - yy1, 0.f) * fmaxf(xx2 - xx1, 0.f);
    float ca = (c.z - c.x) * (c.w - c.y);
    float u = ((fa + ca) - inter) + 1e-8f;
    return inter / u >= 0.7f;
}

__device__ __forceinline__ unsigned long long mk_key(unsigned u, unsigned n) {
    return ((unsigned long long)u << 18) | (unsigned long long)(0x3FFFFu - n);
}

// parallel suffix scan over 256 smem bins (256 threads); bins -> suffix sums
__device__ __forceinline__ void suffix_scan_256(unsigned* bins, int tid) {
    #pragma unroll
    for (int off = 1; off < 256; off <<= 1) {
        unsigned v = (tid + off < 256) ? bins[tid + off] : 0u;
        __syncthreads();
        bins[tid] += v;
        __syncthreads();
    }
}
__device__ __forceinline__ void suffix_pick_256(const unsigned* bins, unsigned K,
                                                int tid, int* s_pick,
                                                unsigned* s_above) {
    unsigned mine = bins[tid];
    unsigned next = (tid == 255) ? 0u : bins[tid + 1];
    if (mine >= K && next < K) { *s_pick = tid; *s_above = next; }
    __syncthreads();
}

// ---------------- K1: hist + (last block) findbins --------------------------
__global__ void k_hist_findbins(const float* __restrict__ probs, int b) {
    __shared__ unsigned sc[256];
    __shared__ int s_pick;
    __shared__ unsigned s_above;
    __shared__ int s_last;
    int tid = threadIdx.x;

    // phase 1: flip + histogram
    {
        const float4* p4 = (const float4*)(probs + (size_t)b * NVAL * 2);
        uint2* u2 = (uint2*)(g_u + b * NVAL);
        const int n2 = NVAL / 2;
        for (int i = blockIdx.x * blockDim.x + tid; i < n2;
             i += gridDim.x * blockDim.x) {
            float4 v = p4[i];
            unsigned ua = flip_f(v.y);
            unsigned ub = flip_f(v.w);
            u2[i] = make_uint2(ua, ub);
            atomicAdd(&g_hist1[b * 65536 + (ua >> 16)], 1u);
            atomicAdd(&g_hist1[b * 65536 + (ub >> 16)], 1u);
        }
    }
    // last-block election
    __threadfence();
    __syncthreads();
    if (tid == 0) {
        unsigned prev = atomicAdd(&g_done1[b], 1u);
        s_last = (prev == HBLK - 1u);
        if (s_last) g_done1[b] = 0u;   // reset for next replay
    }
    __syncthreads();
    if (!s_last) return;

    // phase 2: findbins (exact coarse bins for ranks W and PRE)
    const unsigned* hist = g_hist1 + b * 65536;
    unsigned s = 0;
    int base = tid * 256;
    for (int i = 0; i < 256; ++i) s += hist[base + i];
    sc[tid] = s;
    __syncthreads();
    suffix_scan_256(sc, tid);
    suffix_pick_256(sc, (unsigned)W, tid, &s_pick, &s_above);
    int cw = s_pick; unsigned aw = s_above;
    __syncthreads();
    suffix_pick_256(sc, (unsigned)PRE, tid, &s_pick, &s_above);
    int cp = s_pick; unsigned ap = s_above;
    __syncthreads();

    sc[tid] = hist[cw * 256 + tid];
    __syncthreads();
    suffix_scan_256(sc, tid);
    suffix_pick_256(sc, (unsigned)W - aw, tid, &s_pick, &s_above);
    if (tid == 0) {
        g_b1w[b] = (unsigned)(cw * 256 + s_pick);
        g_abovew[b] = aw + s_above;
    }
    __syncthreads();

    sc[tid] = hist[cp * 256 + tid];
    __syncthreads();
    suffix_scan_256(sc, tid);
    suffix_pick_256(sc, (unsigned)PRE - ap, tid, &s_pick, &s_above);
    if (tid == 0)
        g_b1p[b] = (unsigned)(cp * 256 + s_pick);
}

// ---------------- K2: compact + hist re-zero + (last block) select -----------
__global__ void k_compact_select(int b) {
    __shared__ unsigned su[CAP];      // 32 KB (select phase; reused freely)
    __shared__ unsigned bins[256];
    __shared__ int s_warpoff[8];
    __shared__ int s_base;
    __shared__ int s_pick;
    __shared__ unsigned s_above;
    __shared__ int s_cnt2;
    __shared__ int s_last;

    int tid = threadIdx.x, lane = tid & 31, wid = tid >> 5;

    // ---- compact phase ----
    {
        unsigned T = g_b1p[b] << 16;
        const uint4* u4 = (const uint4*)(g_u + b * NVAL);
        const int n4 = NVAL / 4;
        int base_i = blockIdx.x * 1024;

        uint4 v[4];
        int c = 0;
        #pragma unroll
        for (int k = 0; k < 4; ++k) {
            int i = base_i + k * 256 + tid;
            v[k] = (i < n4) ? u4[i] : make_uint4(0, 0, 0, 0);
            c += (v[k].x >= T) + (v[k].y >= T) + (v[k].z >= T) + (v[k].w >= T);
        }
        int incl = c;
        #pragma unroll
        for (int off = 1; off < 32; off <<= 1) {
            int t = __shfl_up_sync(FULLM, incl, off);
            if (lane >= off) incl += t;
        }
        if (lane == 31) s_warpoff[wid] = incl;
        __syncthreads();
        if (tid == 0) {
            int tot = 0;
            #pragma unroll
            for (int w = 0; w < 8; ++w) {
                int t = s_warpoff[w];
                s_warpoff[w] = tot;
                tot += t;
            }
            s_base = tot ? atomicAdd(&g_candcnt[b], tot) : 0;
        }
        __syncthreads();
        int pos = s_base + s_warpoff[wid] + incl - c;
        #pragma unroll
        for (int k = 0; k < 4; ++k) {
            int i = base_i + k * 256 + tid;
            unsigned n0 = (unsigned)(i * 4);
            if (v[k].x >= T) { if (pos < CAP) g_cand[b * CAP + pos] = mk_key(v[k].x, n0 + 0); ++pos; }
            if (v[k].y >= T) { if (pos < CAP) g_cand[b * CAP + pos] = mk_key(v[k].y, n0 + 1); ++pos; }
            if (v[k].z >= T) { if (pos < CAP) g_cand[b * CAP + pos] = mk_key(v[k].z, n0 + 2); ++pos; }
            if (v[k].w >= T) { if (pos < CAP) g_cand[b * CAP + pos] = mk_key(v[k].w, n0 + 3); ++pos; }
        }
        ((uint4*)(g_hist1 + b * 65536 + blockIdx.x * 1024))[tid] = make_uint4(0, 0, 0, 0);
    }

    // ---- last-block election ----
    __threadfence();
    __syncthreads();
    if (tid == 0) {
        unsigned prev = atomicAdd(&g_done2[b], 1u);
        s_last = (prev == HBLK - 1u);
        if (s_last) g_done2[b] = 0u;
    }
    __syncthreads();
    if (!s_last) return;

    // ---- select phase (exact rank-W threshold + top-set compact) ----
    int cnt = g_candcnt[b];
    if (cnt > CAP) cnt = CAP;
    unsigned b1 = g_b1w[b];
    unsigned K = (unsigned)W - g_abovew[b];

    for (int i = tid; i < cnt; i += 256)
        su[i] = (unsigned)(g_cand[b * CAP + i] >> 18);
    bins[tid] = 0;
    __syncthreads();
    for (int i = tid; i < cnt; i += 256) {
        unsigned u = su[i];
        if ((u >> 16) == b1) atomicAdd(&bins[(u >> 8) & 0xFF], 1u);
    }
    __syncthreads();
    suffix_scan_256(bins, tid);
    suffix_pick_256(bins, K, tid, &s_pick, &s_above);
    unsigned pre = (b1 << 8) | (unsigned)s_pick;
    unsigned K2 = K - s_above;
    __syncthreads();

    bins[tid] = 0;
    __syncthreads();
    for (int i = tid; i < cnt; i += 256) {
        unsigned u = su[i];
        if ((u >> 8) == pre) atomicAdd(&bins[u & 0xFF], 1u);
    }
    __syncthreads();
    suffix_scan_256(bins, tid);
    suffix_pick_256(bins, K2, tid, &s_pick, &s_above);
    unsigned T2 = (pre << 8) | (unsigned)s_pick;
    if (tid == 0) s_cnt2 = 0;
    __syncthreads();

    // warp-aggregated compaction (1 smem atomic per warp-iteration)
    for (int i0 = tid; i0 - tid < cnt; i0 += 256) {
        bool pass = (i0 < cnt) && (su[i0] >= T2);   // key >= (T2<<18) iff u >= T2
        unsigned bal = __ballot_sync(FULLM, pass);
        if (!bal) continue;
        int leader = __ffs(bal) - 1;
        int basep = 0;
        if (lane == leader) basep = atomicAdd(&s_cnt2, __popc(bal));
        basep = __shfl_sync(FULLM, basep, leader);
        if (pass) {
            int pos = basep + __popc(bal & ((1u << lane) - 1u));
            if (pos < CAPW) g_top[b * CAPW + pos] = g_cand[b * CAP + i0];
        }
    }
    __syncthreads();
    if (tid == 0) {
        int tc = s_cnt2;
        g_topcnt[b] = tc;
        g_wvalid[b] = (tc >= W && tc <= CAPW) ? 1 : 0;
    }
}

// ---------------- K3: counting-rank over top set + box + alive ----------------
__global__ void k_rank(const float* __restrict__ bbox,
                       const float* __restrict__ anchors, int b) {
    __shared__ unsigned long long tile[256];
    if (!g_wvalid[b]) return;
    int tc = g_topcnt[b];
    int i = blockIdx.x * blockDim.x + threadIdx.x;
    unsigned long long key = (i < tc) ? g_top[b * CAPW + i] : 0ULL;
    int rank = 0;
    for (int t0 = 0; t0 < tc; t0 += 256) {
        int j = t0 + threadIdx.x;
        tile[threadIdx.x] = (j < tc) ? g_top[b * CAPW + j] : 0ULL;
        __syncthreads();
        int lim = tc - t0; if (lim > 256) lim = 256;
        #pragma unroll 4
        for (int j2 = 0; j2 < lim; ++j2)
            rank += (tile[j2] > key);
        __syncthreads();
    }
    if (i < tc && rank < W) {
        unsigned idx = 0x3FFFFu - (unsigned)(key & 0x3FFFFu);
        float4 box = (idx < (unsigned)NVAL)
            ? compute_box(bbox, anchors, b, (int)idx)
            : make_float4(0.f, 0.f, 0.f, 0.f);
        ((float4*)g_winbox)[b * W + rank] = box;
        if (unflip_f((unsigned)(key >> 18)) >= 0.5f)
            atomicOr(&g_walive[b * 64 + (rank >> 5)], 1u << (rank & 31));
    }
}

// ---------------- K4: windowed suppression matrix build -----------------------
__global__ void k_build(int b) {
    int bx = blockIdx.x, by = blockIdx.y;
    if (bx * 64 + 64 <= by * 128) return;
    __shared__ float4 cb[64];
    __shared__ float  ca[64];
    int t = threadIdx.x;
    int j0 = bx * 64;
    const float4* boxes4 = (const float4*)g_winbox;
    if (t < 64) {
        float4 a = boxes4[b * W + j0 + t];
        cb[t] = a;
        ca[t] = (a.z - a.x) * (a.w - a.y);
    }
    __syncthreads();
    int i = by * 128 + t;
    float4 r = boxes4[b * W + i];
    float ra = (r.z - r.x) * (r.w - r.y);
    unsigned w0 = 0, w1 = 0;
    #pragma unroll 8
    for (int jj = 0; jj < 64; ++jj) {
        int j = j0 + jj;
        bool sup = false;
        if (j > i) {
            float4 c = cb[jj];
            float yy1 = fmaxf(r.x, c.x);
            float xx1 = fmaxf(r.y, c.y);
            float yy2 = fminf(r.z, c.z);
            float xx2 = fminf(r.w, c.w);
            float inter = fmaxf(yy2 - yy1, 0.f) * fmaxf(xx2 - xx1, 0.f);
            float u = ((ra + ca[jj]) - inter) + 1e-8f;
            if (inter >= 0.700007f * u)       sup = true;
            else if (inter <= 0.699993f * u)  sup = false;
            else                              sup = (inter / u >= 0.7f);
        }
        if (jj < 32) w0 |= ((unsigned)sup) << jj;
        else         w1 |= ((unsigned)sup) << (jj - 32);
    }
    uint2* rb = (uint2*)(g_mat + ((size_t)b * W + i) * MWORDS + bx * 2);
    *rb = make_uint2(w0, w1);
}

// ---------------- K5: pipelined full-word frontier NMS ------------------------
__global__ void __launch_bounds__(32, 1) k_nms_fast(float* __restrict__ out, int b) {
    __shared__ int s_picks[PROP];
    int lane = threadIdx.x;
    const float4* wbox4 = (const float4*)g_winbox;

    for (int t = lane; t < PROP * 4; t += 32) out[b * PROP * 4 + t] = 0.f;

    int valid = g_wvalid[b];
    unsigned a0 = g_walive[b * 64 + lane];
    unsigned a1 = g_walive[b * 64 + 32 + lane];
    g_walive[b * 64 + lane] = 0u;
    g_walive[b * 64 + 32 + lane] = 0u;

    int p = 0;
    if (valid) {
        const unsigned* mat = g_mat + (size_t)b * W * MWORDS;
        unsigned c0[32], c1[32], n0[32], n1[32], fw[32];

        unsigned bal0 = __ballot_sync(FULLM, a0 != 0u);
        unsigned bal1 = __ballot_sync(FULLM, a1 != 0u);
        int F = -1;
        if (bal0)      F = __ffs(bal0) - 1;
        else if (bal1) F = 32 + __ffs(bal1) - 1;

        if (F >= 0) {
            {
                const unsigned* rb = mat + (size_t)(F * 32) * MWORDS;
                #pragma unroll
                for (int q = 0; q < 32; ++q) {
                    c0[q] = rb[q * MWORDS + lane];
                    c1[q] = rb[q * MWORDS + 32 + lane];
                }
            }
            while (p < PROP) {
                unsigned w0 = __shfl_sync(FULLM, (F < 32) ? a0 : a1, F & 31);

                int pf = F + 1;
                if (pf < MWORDS) {
                    const unsigned* rb = mat + (size_t)(pf * 32) * MWORDS;
                    #pragma unroll
                    for (int q = 0; q < 32; ++q) {
                        n0[q] = rb[q * MWORDS + lane];
                        n1[q] = rb[q * MWORDS + 32 + lane];
                    }
                }

                #pragma unroll
                for (int q = 0; q < 32; ++q)
                    fw[q] = __shfl_sync(FULLM, (F < 32) ? c0[q] : c1[q], F & 31);

                unsigned tb = w0, acc = 0;
                #pragma unroll
                for (int q = 0; q < 32; ++q) {
                    if ((tb & (1u << q)) && p < PROP) {
                        acc |= 1u << q;
                        if (lane == 0) s_picks[p] = F * 32 + q;
                        ++p;
                        tb &= ~fw[q];
                    }
                }

                unsigned or0 = 0, or1 = 0;
                #pragma unroll
                for (int q = 0; q < 32; ++q) {
                    if (acc & (1u << q)) { or0 |= c0[q]; or1 |= c1[q]; }
                }
                a0 &= ~or0;
                a1 &= ~or1;
                if (F < 32) { if (lane == F) a0 = 0; }
                else        { if (lane == F - 32) a1 = 0; }

                if (p >= PROP) break;

                bal0 = __ballot_sync(FULLM, a0 != 0u);
                bal1 = __ballot_sync(FULLM, a1 != 0u);
                int Fn = -1;
                if (bal0)      Fn = __ffs(bal0) - 1;
                else if (bal1) Fn = 32 + __ffs(bal1) - 1;
                if (Fn < 0) break;

                if (Fn == pf) {
                    #pragma unroll
                    for (int q = 0; q < 32; ++q) { c0[q] = n0[q]; c1[q] = n1[q]; }
                } else {
                    const unsigned* rb = mat + (size_t)(Fn * 32) * MWORDS;
                    #pragma unroll
                    for (int q = 0; q < 32; ++q) {
                        c0[q] = rb[q * MWORDS + lane];
                        c1[q] = rb[q * MWORDS + 32 + lane];
                    }
                }
                F = Fn;
            }
        }
    }

    __syncwarp();
    float4* out4 = (float4*)out;
    for (int q = lane; q < p; q += 32) {
        int pos = s_picks[q];
        out4[b * PROP + q] = wbox4[b * W + pos];
        g_picks[b * PROP + q] = pos;
    }
    if (lane == 0) {
        g_fbcount[b] = p;
        g_fbneed[b] = (p < PROP) ? 1 : 0;
    }
}

// ---------------- K6: exact fallback kernel (early-exits when unneeded) ------
__global__ void k_nms_exact(float* __restrict__ out,
                            const float* __restrict__ bbox,
                            const float* __restrict__ anchors, int b) {
    __shared__ unsigned s_alive[CAP / 32];
    int lane = threadIdx.x;
    int cnt = g_candcnt[b];
    if (cnt > CAP) cnt = CAP;
    if (lane == 0) g_candcnt[b] = 0;   // restore for next replay
    if (!g_fbneed[b]) return;

    const float4* wbox4 = (const float4*)g_winbox;
    int p_fast = g_fbcount[b];
    int p = p_fast;
    float4* fbb4 = (float4*)g_fbb;

    for (int i = lane; i < cnt; i += 32) {
        unsigned long long key = g_cand[b * CAP + i];
        unsigned idx = 0x3FFFFu - (unsigned)(key & 0x3FFFFu);
        fbb4[b * CAP + i] = (idx < (unsigned)NVAL)
            ? compute_box(bbox, anchors, b, (int)idx)
            : make_float4(0.f, 0.f, 0.f, 0.f);
    }
    for (int wd = lane; wd < CAP / 32; wd += 32) s_alive[wd] = 0u;
    __syncwarp();
    for (int i = lane; i < cnt; i += 32) {
        unsigned long long key = g_cand[b * CAP + i];
        int rank = 0;
        for (int j = 0; j < cnt; ++j)
            rank += (g_cand[b * CAP + j] > key);
        bool live = (rank < PRE) &&
                    (unflip_f((unsigned)(key >> 18)) >= 0.5f);
        if (live) atomicOr(&s_alive[i >> 5], 1u << (i & 31));
    }
    __syncwarp();
    for (int q = 0; q < p_fast; ++q) {
        float4 pb = wbox4[b * W + g_picks[b * PROP + q]];
        float pa = (pb.z - pb.x) * (pb.w - pb.y);
        for (int i = lane; i < cnt; i += 32) {
            if (s_alive[i >> 5] & (1u << (i & 31))) {
                if (iou_ge07(pb, pa, fbb4[b * CAP + i]))
                    atomicAnd(&s_alive[i >> 5], ~(1u << (i & 31)));
            }
        }
        __syncwarp();
    }
    while (p < PROP) {
        unsigned long long bestk = 0ULL;
        int besti = -1;
        for (int i = lane; i < cnt; i += 32) {
            if (s_alive[i >> 5] & (1u << (i & 31))) {
                unsigned long long k2 = g_cand[b * CAP + i];
                if (k2 > bestk) { bestk = k2; besti = i; }
            }
        }
        #pragma unroll
        for (int off = 16; off; off >>= 1) {
            unsigned long long ok = __shfl_xor_sync(FULLM, bestk, off);
            int oi = __shfl_xor_sync(FULLM, besti, off);
            if (ok > bestk) { bestk = ok; besti = oi; }
        }
        if (besti < 0) break;
        float4 pb = fbb4[b * CAP + besti];
        if (lane == 0) ((float4*)out)[b * PROP + p] = pb;
        float pa = (pb.z - pb.x) * (pb.w - pb.y);
        for (int i = lane; i < cnt; i += 32) {
            if (s_alive[i >> 5] & (1u << (i & 31))) {
                if (iou_ge07(pb, pa, fbb4[b * CAP + i]))
                    atomicAnd(&s_alive[i >> 5], ~(1u << (i & 31)));
            }
        }
        __syncwarp();
        ++p;
    }
}

// ---------------- launch: 8 forked per-batch stream pipelines ----------------
extern "C" void kernel_launch(void* const* d_in, const int* in_sizes, int n_in,
                              void* d_out, int out_size) {
    const float* probs   = (const float*)d_in[0];
    const float* bbox    = (const float*)d_in[1];
    const float* anchors = (const float*)d_in[2];
    float* out = (float*)d_out;
    (void)in_sizes; (void)n_in; (void)out_size;

    cudaEventRecord(g_ss.root, 0);
    for (int b = 0; b < BATCH; ++b) {
        cudaStream_t st = g_ss.s[b];
        cudaStreamWaitEvent(st, g_ss.root, 0);

        k_hist_findbins<<<HBLK, 256, 0, st>>>(probs, b);
        k_compact_select<<<HBLK, 256, 0, st>>>(b);
        k_rank<<<CAPW / 256, 256, 0, st>>>(bbox, anchors, b);
        dim3 gridB(W / 64, W / 128);
        k_build<<<gridB, 128, 0, st>>>(b);
        k_nms_fast<<<1, 32, 0, st>>>(out, b);
        k_nms_exact<<<1, 32, 0, st>>>(out, bbox, anchors, b);

        cudaEventRecord(g_ss.done[b], st);
    }
    for (int b = 0; b < BATCH; ++b)
        cudaStreamWaitEvent((cudaStream_t)0, g_ss.done[b], 0);
}